// round 3
// baseline (speedup 1.0000x reference)
#include <cuda_runtime.h>

// loss = M * (1/(999N) + 1/N), M = #pixels where trunc-index(r) != trunc-index(t).
// One warp per block: warp REDUX -> fused 64-bit (count<<32|done) atomic;
// last block writes the scalar with host-precomputed reciprocals and resets
// the accumulator (deterministic across CUDA-graph replays).

__device__ unsigned long long g_acc = 0ull;  // [count:32 | blocks_done:32]

static __device__ __forceinline__ int quant_idx(float x) {
    // match reference: x*1000 - 1, clamp below at 0, truncate (floor for v>=0)
    float v = __fsub_rn(__fmul_rn(x, 1000.0f), 1.0f);
    v = v < 0.0f ? 0.0f : v;
    return (int)v;
}

__global__ void __launch_bounds__(32)
true3d_loss_kernel(const float* __restrict__ r,
                   const float* __restrict__ t,
                   float* __restrict__ out, int N,
                   float inv_zero, float inv_nonzero) {
    const int lane = threadIdx.x;            // 0..31, one warp per block
    const int N4 = N >> 2;
    const float4* __restrict__ r4 = (const float4*)r;
    const float4* __restrict__ t4 = (const float4*)t;

    // 8 float4 per thread per input, warp-coalesced, all loads front-batched.
    const int base = blockIdx.x * 256;       // in float4 units (8 iters * 32 lanes)
    float4 a[8], b[8];
    bool valid[8];
    #pragma unroll
    for (int k = 0; k < 8; k++) {
        int i = base + k * 32 + lane;
        valid[k] = (i < N4);
        int ic = valid[k] ? i : 0;
        a[k] = __ldg(&r4[ic]);
        b[k] = __ldg(&t4[ic]);
    }

    unsigned int cnt = 0;
    #pragma unroll
    for (int k = 0; k < 8; k++) {
        if (valid[k]) {
            cnt += (quant_idx(a[k].x) != quant_idx(b[k].x));
            cnt += (quant_idx(a[k].y) != quant_idx(b[k].y));
            cnt += (quant_idx(a[k].z) != quant_idx(b[k].z));
            cnt += (quant_idx(a[k].w) != quant_idx(b[k].w));
        }
    }

    // scalar tail (N not a multiple of 4) — empty for N=90112
    for (int i = (N4 << 2) + blockIdx.x * 32 + lane; i < N;
         i += gridDim.x * 32) {
        cnt += (quant_idx(__ldg(&r[i])) != quant_idx(__ldg(&t[i])));
    }

    cnt = __reduce_add_sync(0xFFFFFFFFu, cnt);   // single REDUX

    if (lane == 0) {
        unsigned long long old =
            atomicAdd(&g_acc, ((unsigned long long)cnt << 32) | 1ull);
        if ((unsigned int)(old & 0xFFFFFFFFull) == gridDim.x - 1) {
            unsigned int M = (unsigned int)(old >> 32) + cnt;
            float fM = (float)M;
            out[0] = __fmaf_rn(fM, inv_zero, fM * inv_nonzero);
            atomicExch(&g_acc, 0ull);            // reset for next replay
        }
    }
}

extern "C" void kernel_launch(void* const* d_in, const int* in_sizes, int n_in,
                              void* d_out, int out_size) {
    const float* rec = (const float*)d_in[0];
    const float* tgt = (const float*)d_in[1];
    float* out = (float*)d_out;
    const int N = in_sizes[0];

    const float fN = (float)N;
    const float inv_zero = 1.0f / (999.0f * fN);
    const float inv_nonzero = 1.0f / fN;

    // one warp per block, 32 floats (8 float4) per thread per input
    int blocks = (N + 1023) / 1024;          // 88 for N=90112 (exact fit)
    if (blocks < 1) blocks = 1;

    true3d_loss_kernel<<<blocks, 32>>>(rec, tgt, out, N, inv_zero, inv_nonzero);
}

// round 4
// speedup vs baseline: 1.3092x; 1.3092x over previous
#include <cuda_runtime.h>

// loss = M * (1/(999N) + 1/N), M = #pixels where trunc-index(r) != trunc-index(t).
// 88 blocks x 256 threads, one float4-pair per thread (max parallelism — the
// R3 one-warp experiment proved per-thread batching loses to thread count).
// No smem block reduce: each warp's lane 0 sends its REDUX sum straight into
// a fused 64-bit (count<<32 | warps_done) atomic; the 704th warp finalizes
// and resets the accumulator (deterministic across CUDA-graph replays).

__device__ unsigned long long g_acc = 0ull;  // [count:32 | warps_done:32]

static __device__ __forceinline__ int quant_idx(float x) {
    // match reference: x*1000 - 1, clamp below at 0, truncate (floor for v>=0)
    float v = __fsub_rn(__fmul_rn(x, 1000.0f), 1.0f);
    v = v < 0.0f ? 0.0f : v;
    return (int)v;
}

__global__ void __launch_bounds__(256)
true3d_loss_kernel(const float* __restrict__ r,
                   const float* __restrict__ t,
                   float* __restrict__ out, int N,
                   unsigned int total_warps,
                   float inv_zero, float inv_nonzero) {
    const int tid = blockIdx.x * blockDim.x + threadIdx.x;
    const int stride = gridDim.x * blockDim.x;
    const int N4 = N >> 2;

    const float4* __restrict__ r4 = (const float4*)r;
    const float4* __restrict__ t4 = (const float4*)t;

    unsigned int cnt = 0;
    for (int i = tid; i < N4; i += stride) {   // single iteration at N=90112
        float4 a = __ldg(&r4[i]);
        float4 b = __ldg(&t4[i]);
        cnt += (quant_idx(a.x) != quant_idx(b.x));
        cnt += (quant_idx(a.y) != quant_idx(b.y));
        cnt += (quant_idx(a.z) != quant_idx(b.z));
        cnt += (quant_idx(a.w) != quant_idx(b.w));
    }
    // scalar tail (N not a multiple of 4) — empty for N=90112
    for (int i = (N4 << 2) + tid; i < N; i += stride) {
        cnt += (quant_idx(__ldg(&r[i])) != quant_idx(__ldg(&t[i])));
    }

    cnt = __reduce_add_sync(0xFFFFFFFFu, cnt);   // warp REDUX

    if ((threadIdx.x & 31) == 0) {
        // fused count+done atomic, one per warp — no smem, no __syncthreads
        unsigned long long old =
            atomicAdd(&g_acc, ((unsigned long long)cnt << 32) | 1ull);
        if ((unsigned int)(old & 0xFFFFFFFFull) == total_warps - 1) {
            unsigned int M = (unsigned int)(old >> 32) + cnt;
            float fM = (float)M;
            out[0] = __fmaf_rn(fM, inv_zero, fM * inv_nonzero);
            atomicExch(&g_acc, 0ull);            // reset for next replay
        }
    }
}

extern "C" void kernel_launch(void* const* d_in, const int* in_sizes, int n_in,
                              void* d_out, int out_size) {
    const float* rec = (const float*)d_in[0];
    const float* tgt = (const float*)d_in[1];
    float* out = (float*)d_out;
    const int N = in_sizes[0];

    const float fN = (float)N;
    const float inv_zero = 1.0f / (999.0f * fN);
    const float inv_nonzero = 1.0f / fN;

    const int threads = 256;
    int blocks = (N / 4 + threads - 1) / threads;  // 88 for N=90112 (exact fit)
    if (blocks < 1) blocks = 1;
    if (blocks > 1024) blocks = 1024;
    const unsigned int total_warps = (unsigned int)blocks * (threads / 32);

    true3d_loss_kernel<<<blocks, threads>>>(rec, tgt, out, N, total_warps,
                                            inv_zero, inv_nonzero);
}